// round 4
// baseline (speedup 1.0000x reference)
#include <cuda_runtime.h>
#include <math.h>

#define MEM_DIM 2000
#define FEA     512
#define NB      32
#define HW      1024
#define NTOK    (NB * HW)      // 32768
#define THRES   0.0025f
#define EPSV    1e-12f
#define FIX_CAP 65536

// ---------------- scratch (static device allocations) ----------------
__device__ float  g_E[(size_t)NTOK * MEM_DIM];   // exp(logits), 262 MB
__device__ float  g_invS[NTOK];
__device__ double g_S64[NTOK];
__device__ float  g_invT[NTOK];
__device__ unsigned g_fix[FIX_CAP];
__device__ unsigned g_nfix;

// ---------------- packed f32x2 helpers ----------------
__device__ __forceinline__ unsigned long long pack2(float v) {
    unsigned long long r;
    unsigned u = __float_as_uint(v);
    asm("mov.b64 %0, {%1, %1};" : "=l"(r) : "r"(u));
    return r;
}
__device__ __forceinline__ void fma2(unsigned long long &c, unsigned long long a, unsigned long long b) {
    asm("fma.rn.f32x2 %0, %1, %2, %0;" : "+l"(c) : "l"(a), "l"(b));
}
__device__ __forceinline__ float lo2(unsigned long long v) { return __uint_as_float((unsigned)v); }
__device__ __forceinline__ float hi2(unsigned long long v) { return __uint_as_float((unsigned)(v >> 32)); }

// ---------------- kernel A: logits GEMM + exp ----------------
// E[n, m] = exp( sum_c xf[n,c] * W[m,c] ), xf[n,c] = x[b, c, hw], n = b*1024 + hw
#define BM 128
#define BN 128
#define BKK 16

__global__ __launch_bounds__(256, 2) void k_gemm_exp(const float* __restrict__ x,
                                                     const float* __restrict__ w) {
    __shared__ float As[BKK][BM];
    __shared__ float Bs[BKK][BN];
    const int tid = threadIdx.x;
    const int tx = tid & 15;          // column group (m)
    const int ty = tid >> 4;          // row group (n)
    const int m0 = blockIdx.x * BN;
    const int n0 = blockIdx.y * BM;
    const int b  = n0 >> 10;
    const int hw0 = n0 & 1023;
    const float* xb = x + (size_t)b * FEA * HW + hw0;

    unsigned long long acc[8][4];
#pragma unroll
    for (int i = 0; i < 8; i++)
#pragma unroll
        for (int j = 0; j < 4; j++) acc[i][j] = 0ull;

    for (int k0 = 0; k0 < FEA; k0 += BKK) {
#pragma unroll
        for (int p = 0; p < 2; p++) {
            int q = tid + p * 256;
            int c = q >> 5;
            int seg = q & 31;
            float4 v = *(const float4*)(xb + (size_t)(k0 + c) * HW + seg * 4);
            *(float4*)&As[c][seg * 4] = v;
        }
#pragma unroll
        for (int p = 0; p < 2; p++) {
            int q = tid + p * 256;
            int ml = q >> 2;
            int c4 = q & 3;
            int m = m0 + ml;
            float4 v = make_float4(0.f, 0.f, 0.f, 0.f);
            if (m < MEM_DIM) v = *(const float4*)(w + (size_t)m * FEA + k0 + c4 * 4);
            Bs[c4 * 4 + 0][ml] = v.x;
            Bs[c4 * 4 + 1][ml] = v.y;
            Bs[c4 * 4 + 2][ml] = v.z;
            Bs[c4 * 4 + 3][ml] = v.w;
        }
        __syncthreads();
#pragma unroll
        for (int k = 0; k < BKK; k++) {
            float4 a0 = *(const float4*)&As[k][ty * 8];
            float4 a1 = *(const float4*)&As[k][ty * 8 + 4];
            const unsigned long long* bp = (const unsigned long long*)&Bs[k][tx * 8];
            unsigned long long b0 = bp[0], b1 = bp[1], b2 = bp[2], b3 = bp[3];
            float av[8] = {a0.x, a0.y, a0.z, a0.w, a1.x, a1.y, a1.z, a1.w};
#pragma unroll
            for (int i = 0; i < 8; i++) {
                unsigned long long ap = pack2(av[i]);
                fma2(acc[i][0], ap, b0);
                fma2(acc[i][1], ap, b1);
                fma2(acc[i][2], ap, b2);
                fma2(acc[i][3], ap, b3);
            }
        }
        __syncthreads();
    }
    const int m = m0 + tx * 8;
    if (m < MEM_DIM) {
#pragma unroll
        for (int i = 0; i < 8; i++) {
            int n = n0 + ty * 8 + i;
            float4 o0, o1;
            o0.x = expf(lo2(acc[i][0])); o0.y = expf(hi2(acc[i][0]));
            o0.z = expf(lo2(acc[i][1])); o0.w = expf(hi2(acc[i][1]));
            o1.x = expf(lo2(acc[i][2])); o1.y = expf(hi2(acc[i][2]));
            o1.z = expf(lo2(acc[i][3])); o1.w = expf(hi2(acc[i][3]));
            float* dst = &g_E[(size_t)n * MEM_DIM + m];
            *(float4*)dst = o0;
            *(float4*)(dst + 4) = o1;
        }
    }
}

// ---------------- kernel B1: softmax denominators (fp64 accumulate) ----------------
__global__ __launch_bounds__(256) void k_rowsum() {
    int n = blockIdx.x * 8 + (threadIdx.x >> 5);
    int lane = threadIdx.x & 31;
    const float* row = g_E + (size_t)n * MEM_DIM;
    double s = 0.0;
    for (int j = lane; j < MEM_DIM; j += 32) s += (double)row[j];
#pragma unroll
    for (int o = 16; o; o >>= 1) s += __shfl_xor_sync(0xffffffffu, s, o);
    if (lane == 0) {
        g_S64[n]  = s;
        g_invS[n] = (float)(1.0 / s);
    }
}

// ---------------- counter reset ----------------
__global__ void k_reset() { g_nfix = 0u; }

// ---------------- kernel B1b: flag borderline values ----------------
// |att - THRES| < 5e-7  (≈ 2e-4 relative) -> needs fp64 refinement
__global__ __launch_bounds__(256) void k_scan() {
    int n = blockIdx.x;
    float is = g_invS[n];
    const float* row = g_E + (size_t)n * MEM_DIM;
    for (int j = threadIdx.x; j < MEM_DIM; j += 256) {
        float att = row[j] * is;
        if (fabsf(att - THRES) < 5e-7f) {
            unsigned idx = atomicAdd(&g_nfix, 1u);
            if (idx < FIX_CAP) g_fix[idx] = ((unsigned)n << 11) | (unsigned)j;
        }
    }
}

// ---------------- kernel B1c: fp64 refinement of borderline values ----------------
__global__ __launch_bounds__(256) void k_refine(const float* __restrict__ x,
                                                const float* __restrict__ w) {
    unsigned total = g_nfix;
    if (total > FIX_CAP) total = FIX_CAP;
    int lane = threadIdx.x & 31;
    int warp = (blockIdx.x * 256 + threadIdx.x) >> 5;
    const int nwarps = 64 * 8;   // 64 blocks * 8 warps
    for (unsigned i = warp; i < total; i += nwarps) {
        unsigned code = g_fix[i];
        int n = code >> 11;
        int m = code & 2047;
        int b = n >> 10, hw = n & 1023;
        const float* xr = x + (size_t)b * FEA * HW + hw;
        const float* wr = w + (size_t)m * FEA;
        double s = 0.0;
#pragma unroll
        for (int k = 0; k < 16; k++) {
            int c = lane * 16 + k;
            s += (double)xr[(size_t)c * HW] * (double)wr[c];
        }
#pragma unroll
        for (int o = 16; o; o >>= 1) s += __shfl_xor_sync(0xffffffffu, s, o);
        if (lane == 0) {
            double S = g_S64[n];
            double att = exp(s) / S;
            const double T = 0.0025, MARGIN = 5e-9;
            double att_f = att;
            if (att > T) { if (att < T + MARGIN) att_f = T + MARGIN; }
            else         { if (att > T - MARGIN) att_f = T - MARGIN; }
            g_E[(size_t)n * MEM_DIM + m] = (float)(att_f * S);
        }
    }
}

// ---------------- kernel B2: shrink L1 norms ----------------
__global__ __launch_bounds__(256) void k_rownorm() {
    int n = blockIdx.x * 8 + (threadIdx.x >> 5);
    int lane = threadIdx.x & 31;
    const float* row = g_E + (size_t)n * MEM_DIM;
    float is = g_invS[n];
    float t = 0.f;
    for (int j = lane; j < MEM_DIM; j += 32) {
        float att = row[j] * is;
        float d = att - THRES;
        if (d > 0.f) t += d * att / (d + EPSV);
    }
#pragma unroll
    for (int o = 16; o; o >>= 1) t += __shfl_xor_sync(0xffffffffu, t, o);
    if (lane == 0) g_invT[n] = 1.0f / fmaxf(t, EPSV);
}

// ---------------- kernel C: att output (transposed to NCHW) ----------------
__global__ __launch_bounds__(256) void k_att_out(float* __restrict__ att_out) {
    __shared__ float s[32][65];
    int m0  = blockIdx.x * 64;
    int hw0 = blockIdx.y * 32;
    int b   = blockIdx.z;
    int n0  = b * HW + hw0;
    for (int idx = threadIdx.x; idx < 32 * 64; idx += 256) {
        int i = idx >> 6, j = idx & 63;
        int m = m0 + j;
        float o = 0.f;
        if (m < MEM_DIM) {
            int n = n0 + i;
            float att = g_E[(size_t)n * MEM_DIM + m] * g_invS[n];
            float d = att - THRES;
            if (d > 0.f) o = (d * att / (d + EPSV)) * g_invT[n];
        }
        s[i][j] = o;
    }
    __syncthreads();
    for (int idx = threadIdx.x; idx < 32 * 64; idx += 256) {
        int j = idx >> 5, i = idx & 31;
        int m = m0 + j;
        if (m < MEM_DIM)
            att_out[((size_t)b * MEM_DIM + m) * HW + hw0 + i] = s[i][j];
    }
}

// ---------------- kernel D: sparse y = att' @ W (deterministic scan) ----------------
__global__ __launch_bounds__(256) void k_y(const float* __restrict__ w,
                                           float* __restrict__ y_out) {
    __shared__ float ys[8][513];
    int n0 = blockIdx.x * 8;
    int b = n0 >> 10, hw0 = n0 & 1023;
    int wid = threadIdx.x >> 5, lane = threadIdx.x & 31;
    int n = n0 + wid;
    float is = g_invS[n], it = g_invT[n];
#pragma unroll
    for (int k = 0; k < 16; k++) ys[wid][lane + k * 32] = 0.f;
    const float* row = g_E + (size_t)n * MEM_DIM;
    for (int j0 = 0; j0 < MEM_DIM; j0 += 32) {
        int m = j0 + lane;
        float e = (m < MEM_DIM) ? row[m] : 0.f;
        float att = e * is;
        float d = att - THRES;
        unsigned hits = __ballot_sync(0xffffffffu, d > 0.f);
        while (hits) {
            int bit = __ffs(hits) - 1;
            hits &= hits - 1;
            float ad = __shfl_sync(0xffffffffu, d, bit);
            float aa = __shfl_sync(0xffffffffu, att, bit);
            float av = (ad * aa / (ad + EPSV)) * it;
            const float* wr = w + (size_t)(j0 + bit) * FEA;
#pragma unroll
            for (int k = 0; k < 16; k++)
                ys[wid][lane + k * 32] += av * wr[lane + k * 32];
        }
    }
    __syncthreads();
    for (int idx = threadIdx.x; idx < 8 * FEA; idx += 256) {
        int i = idx & 7, c = idx >> 3;
        y_out[(size_t)b * FEA * HW + (size_t)c * HW + hw0 + i] = ys[i][c];
    }
}

// ---------------- launcher ----------------
extern "C" void kernel_launch(void* const* d_in, const int* in_sizes, int n_in,
                              void* d_out, int out_size) {
    const float* x = (const float*)d_in[0];
    const float* w = (const float*)d_in[1];
    if (n_in >= 2 && in_sizes[0] == MEM_DIM * FEA && in_sizes[1] != MEM_DIM * FEA) {
        const float* t = x; x = w; w = t;
    }
    float* y_out   = (float*)d_out;                       // 32*512*32*32
    float* att_out = y_out + (size_t)NB * FEA * HW;       // 32*2000*32*32

    dim3 gA((MEM_DIM + BN - 1) / BN, NTOK / BM);          // (16, 256)
    k_gemm_exp<<<gA, 256>>>(x, w);
    k_rowsum<<<NTOK / 8, 256>>>();
    k_reset<<<1, 1>>>();
    k_scan<<<NTOK, 256>>>();
    k_refine<<<64, 256>>>(x, w);
    k_rownorm<<<NTOK / 8, 256>>>();
    k_att_out<<<dim3((MEM_DIM + 63) / 64, HW / 32, NB), 256>>>(att_out);
    k_y<<<NTOK / 8, 256>>>(w, y_out);
}

// round 5
// speedup vs baseline: 1.0587x; 1.0587x over previous
#include <cuda_runtime.h>
#include <math.h>

#define MEM_DIM 2000
#define MPAD    2048
#define FEA     512
#define NB      32
#define HW      1024
#define NTOK    (NB * HW)      // 32768
#define THRES   0.0025f
#define EPSV    1e-12f
#define FIX_CAP 65536

// ---------------- scratch (static device allocations) ----------------
__device__ float  g_E[(size_t)NTOK * MEM_DIM];   // exp(logits), 262 MB
__device__ float  g_Wt[(size_t)FEA * MPAD];      // W transposed+padded, 4 MB
__device__ float  g_invS[NTOK];
__device__ double g_S64[NTOK];
__device__ float  g_invT[NTOK];
__device__ unsigned g_fix[FIX_CAP];
__device__ unsigned g_nfix;

// ---------------- helpers ----------------
__device__ __forceinline__ unsigned long long pack2(float v) {
    unsigned long long r;
    unsigned u = __float_as_uint(v);
    asm("mov.b64 %0, {%1, %1};" : "=l"(r) : "r"(u));
    return r;
}
__device__ __forceinline__ void fma2(unsigned long long &c, unsigned long long a, unsigned long long b) {
    asm("fma.rn.f32x2 %0, %1, %2, %0;" : "+l"(c) : "l"(a), "l"(b));
}
__device__ __forceinline__ float lo2(unsigned long long v) { return __uint_as_float((unsigned)v); }
__device__ __forceinline__ float hi2(unsigned long long v) { return __uint_as_float((unsigned)(v >> 32)); }

__device__ __forceinline__ unsigned sm2u(const void* p) {
    return (unsigned)__cvta_generic_to_shared(p);
}
#define CPA16(dst, src) asm volatile("cp.async.cg.shared.global [%0], [%1], 16;" :: "r"(dst), "l"(src))
#define CPCOMMIT()      asm volatile("cp.async.commit_group;")
#define CPWAIT(n)       asm volatile("cp.async.wait_group %0;" :: "n"(n))

// ---------------- kernel P: W[2000][512] -> Wt[512][2048] (pad zeros) -------
__global__ __launch_bounds__(256) void k_prep(const float* __restrict__ w) {
    __shared__ float t[32][33];
    int m0 = blockIdx.x * 32;
    int k0 = blockIdx.y * 32;
    int tx = threadIdx.x & 31, ty = threadIdx.x >> 5;   // 32 x 8
#pragma unroll
    for (int j = 0; j < 32; j += 8) {
        int m = m0 + ty + j;
        t[ty + j][tx] = (m < MEM_DIM) ? w[(size_t)m * FEA + k0 + tx] : 0.f;
    }
    __syncthreads();
#pragma unroll
    for (int j = 0; j < 32; j += 8)
        g_Wt[(size_t)(k0 + ty + j) * MPAD + m0 + tx] = t[tx][ty + j];
}

// ---------------- kernel A: logits GEMM + exp --------------------------------
// E[n, m] = exp( sum_c x[b,c,hw] * W[m,c] ),  n = b*1024 + hw
#define BM 128
#define BN 128
#define BKK 16
#define NKT (FEA / BKK)   // 32

__global__ __launch_bounds__(256, 2) void k_gemm_exp(const float* __restrict__ x) {
    __shared__ float As[2][BKK][BM];
    __shared__ float Bs[2][BKK][BN];
    const int tid = threadIdx.x;
    const int tx = tid & 15;
    const int ty = tid >> 4;
    const int m0 = blockIdx.x * BN;
    const int n0 = blockIdx.y * BM;
    const int b  = n0 >> 10;
    const int hw0 = n0 & 1023;
    const float* xb = x + (size_t)b * FEA * HW + hw0;

    // per-thread load slots (2 for A, 2 for B)
    const int c0  = tid >> 5;              // 0..7
    const int sg0 = (tid & 31) * 4;        // 0..124
    const int c1  = c0 + 8;

    unsigned long long acc[8][4];
#pragma unroll
    for (int i = 0; i < 8; i++)
#pragma unroll
        for (int j = 0; j < 4; j++) acc[i][j] = 0ull;

    // prologue: stage 0
    {
        CPA16(sm2u(&As[0][c0][sg0]), xb + (size_t)c0 * HW + sg0);
        CPA16(sm2u(&As[0][c1][sg0]), xb + (size_t)c1 * HW + sg0);
        CPA16(sm2u(&Bs[0][c0][sg0]), g_Wt + (size_t)c0 * MPAD + m0 + sg0);
        CPA16(sm2u(&Bs[0][c1][sg0]), g_Wt + (size_t)c1 * MPAD + m0 + sg0);
        CPCOMMIT();
    }

    for (int it = 0; it < NKT; it++) {
        const int cur = it & 1;
        if (it + 1 < NKT) {
            const int nb = cur ^ 1;
            const int k1 = (it + 1) * BKK;
            CPA16(sm2u(&As[nb][c0][sg0]), xb + (size_t)(k1 + c0) * HW + sg0);
            CPA16(sm2u(&As[nb][c1][sg0]), xb + (size_t)(k1 + c1) * HW + sg0);
            CPA16(sm2u(&Bs[nb][c0][sg0]), g_Wt + (size_t)(k1 + c0) * MPAD + m0 + sg0);
            CPA16(sm2u(&Bs[nb][c1][sg0]), g_Wt + (size_t)(k1 + c1) * MPAD + m0 + sg0);
            CPCOMMIT();
            CPWAIT(1);
        } else {
            CPWAIT(0);
        }
        __syncthreads();
#pragma unroll
        for (int k = 0; k < BKK; k++) {
            float4 a0 = *(const float4*)&As[cur][k][ty * 8];
            float4 a1 = *(const float4*)&As[cur][k][ty * 8 + 4];
            const unsigned long long* bp = (const unsigned long long*)&Bs[cur][k][tx * 8];
            unsigned long long b0 = bp[0], b1 = bp[1], b2 = bp[2], b3 = bp[3];
            float av[8] = {a0.x, a0.y, a0.z, a0.w, a1.x, a1.y, a1.z, a1.w};
#pragma unroll
            for (int i = 0; i < 8; i++) {
                unsigned long long ap = pack2(av[i]);
                fma2(acc[i][0], ap, b0);
                fma2(acc[i][1], ap, b1);
                fma2(acc[i][2], ap, b2);
                fma2(acc[i][3], ap, b3);
            }
        }
        __syncthreads();
    }

    const int m = m0 + tx * 8;
    if (m < MEM_DIM) {
#pragma unroll
        for (int i = 0; i < 8; i++) {
            int n = n0 + ty * 8 + i;
            float4 o0, o1;
            o0.x = __expf(lo2(acc[i][0])); o0.y = __expf(hi2(acc[i][0]));
            o0.z = __expf(lo2(acc[i][1])); o0.w = __expf(hi2(acc[i][1]));
            o1.x = __expf(lo2(acc[i][2])); o1.y = __expf(hi2(acc[i][2]));
            o1.z = __expf(lo2(acc[i][3])); o1.w = __expf(hi2(acc[i][3]));
            float* dst = &g_E[(size_t)n * MEM_DIM + m];
            *(float4*)dst = o0;
            *(float4*)(dst + 4) = o1;
        }
    }
}

// ---------------- counter reset ----------------
__global__ void k_reset() { g_nfix = 0u; }

// ---------------- kernel B: fused rowsum (fp64) + borderline scan + shrink norm
// warp per row; row lives in 64 registers (one global pass)
__global__ __launch_bounds__(256) void k_stats() {
    int n = blockIdx.x * 8 + (threadIdx.x >> 5);
    int lane = threadIdx.x & 31;
    const float4* row4 = (const float4*)(g_E + (size_t)n * MEM_DIM);

    float4 v[16];
#pragma unroll
    for (int i = 0; i < 15; i++) v[i] = row4[lane + 32 * i];
    v[15] = (lane < 20) ? row4[lane + 480] : make_float4(0.f, 0.f, 0.f, 0.f);

    // fp64 sum (two interleaved accumulators)
    double s0 = 0.0, s1 = 0.0;
#pragma unroll
    for (int i = 0; i < 16; i++) {
        s0 += (double)v[i].x; s1 += (double)v[i].y;
        s0 += (double)v[i].z; s1 += (double)v[i].w;
    }
    double s = s0 + s1;
#pragma unroll
    for (int o = 16; o; o >>= 1) s += __shfl_xor_sync(0xffffffffu, s, o);
    float is = (float)(1.0 / s);

    // shrink norm + borderline scan from registers
    float t = 0.f;
#pragma unroll
    for (int i = 0; i < 16; i++) {
        float e[4] = {v[i].x, v[i].y, v[i].z, v[i].w};
#pragma unroll
        for (int c = 0; c < 4; c++) {
            float att = e[c] * is;
            float d = att - THRES;
            if (d > 0.f) t += d * att / (d + EPSV);
            if (fabsf(att - THRES) < 5e-7f) {
                int j = 4 * (lane + 32 * i) + c;
                if (j < MEM_DIM) {
                    unsigned idx = atomicAdd(&g_nfix, 1u);
                    if (idx < FIX_CAP) g_fix[idx] = ((unsigned)n << 11) | (unsigned)j;
                }
            }
        }
    }
#pragma unroll
    for (int o = 16; o; o >>= 1) t += __shfl_xor_sync(0xffffffffu, t, o);
    if (lane == 0) {
        g_S64[n]  = s;
        g_invS[n] = is;
        g_invT[n] = 1.0f / fmaxf(t, EPSV);
    }
}

// ---------------- kernel B2: fp64 refinement (patch E) ----------------
__global__ __launch_bounds__(256) void k_refine_patch(const float* __restrict__ x,
                                                      const float* __restrict__ w) {
    unsigned total = g_nfix;
    if (total > FIX_CAP) total = FIX_CAP;
    int lane = threadIdx.x & 31;
    int warp = (blockIdx.x * 256 + threadIdx.x) >> 5;
    const int nwarps = 64 * 8;
    for (unsigned i = warp; i < total; i += nwarps) {
        unsigned code = g_fix[i];
        int n = code >> 11;
        int m = code & 2047;
        int b = n >> 10, hw = n & 1023;
        const float* xr = x + (size_t)b * FEA * HW + hw;
        const float* wr = w + (size_t)m * FEA;
        double s = 0.0;
#pragma unroll
        for (int k = 0; k < 16; k++) {
            int c = lane * 16 + k;
            s += (double)xr[(size_t)c * HW] * (double)wr[c];
        }
#pragma unroll
        for (int o = 16; o; o >>= 1) s += __shfl_xor_sync(0xffffffffu, s, o);
        if (lane == 0) {
            double S = g_S64[n];
            double att = exp(s) / S;
            const double T = 0.0025, MARGIN = 5e-9;
            double att_f = att;
            if (att > T) { if (att < T + MARGIN) att_f = T + MARGIN; }
            else         { if (att > T - MARGIN) att_f = T - MARGIN; }
            g_E[(size_t)n * MEM_DIM + m] = (float)(att_f * S);
        }
    }
}

// ---------------- kernel B3: recompute shrink norm for patched rows ----------
__global__ __launch_bounds__(256) void k_refine_norm() {
    unsigned total = g_nfix;
    if (total > FIX_CAP) total = FIX_CAP;
    int lane = threadIdx.x & 31;
    int warp = (blockIdx.x * 256 + threadIdx.x) >> 5;
    const int nwarps = 64 * 8;
    for (unsigned i = warp; i < total; i += nwarps) {
        int n = g_fix[i] >> 11;
        const float* row = g_E + (size_t)n * MEM_DIM;
        float is = g_invS[n];
        float t = 0.f;
        for (int j = lane; j < MEM_DIM; j += 32) {
            float att = row[j] * is;
            float d = att - THRES;
            if (d > 0.f) t += d * att / (d + EPSV);
        }
#pragma unroll
        for (int o = 16; o; o >>= 1) t += __shfl_xor_sync(0xffffffffu, t, o);
        if (lane == 0) g_invT[n] = 1.0f / fmaxf(t, EPSV);
    }
}

// ---------------- kernel C: fused att transpose-out + sparse y ----------------
struct SmemC {
    float ys[32][520];        // y accumulators (32 tokens x 512 ch)
    float trans[32][65];      // att transpose staging
    float sInv[32];
    float tInv[32];
    unsigned cnt;
    unsigned pad_;
    uint2 list[2048];         // survivor list: (token<<11|m, value)
};

__global__ __launch_bounds__(256) void k_out(const float* __restrict__ w,
                                             float* __restrict__ y_out,
                                             float* __restrict__ att_out) {
    extern __shared__ char smem_raw[];
    SmemC* S = (SmemC*)smem_raw;
    const int tid = threadIdx.x;
    const int wid = tid >> 5, lane = tid & 31;
    const int n0 = blockIdx.x * 32;
    const int b = n0 >> 10, hw0 = n0 & 1023;

    // init
    {
        float4* yp = (float4*)S->ys;
        for (int idx = tid; idx < 32 * 130; idx += 256)
            yp[idx] = make_float4(0.f, 0.f, 0.f, 0.f);
        if (tid < 32) {
            S->sInv[tid] = g_invS[n0 + tid];
            S->tInv[tid] = g_invT[n0 + tid];
        }
    }
    __syncthreads();

    const int moff = tid & 63;
    const int trow = tid >> 6;   // 0..3
    const int i2 = tid & 31;

    for (int mt = 0; mt < MEM_DIM; mt += 64) {
        if (tid == 0) S->cnt = 0;
        __syncthreads();
        // compute att tile, stage transpose, collect survivors
#pragma unroll
        for (int p = 0; p < 8; p++) {
            int i = p * 4 + trow;
            int m = mt + moff;
            float o = 0.f;
            if (m < MEM_DIM) {
                float e = g_E[(size_t)(n0 + i) * MEM_DIM + m];
                float att = e * S->sInv[i];
                float d = att - THRES;
                if (d > 0.f) {
                    o = (d * att / (d + EPSV)) * S->tInv[i];
                    unsigned slot = atomicAdd(&S->cnt, 1u);
                    S->list[slot] = make_uint2(((unsigned)i << 11) | (unsigned)m,
                                               __float_as_uint(o));
                }
            }
            S->trans[i][moff] = o;
        }
        __syncthreads();
        // write att (transposed -> NCHW, coalesced over hw)
#pragma unroll
        for (int p = 0; p < 8; p++) {
            int mloc = (tid >> 5) + p * 8;
            int m = mt + mloc;
            if (m < MEM_DIM)
                att_out[((size_t)b * MEM_DIM + m) * HW + hw0 + i2] = S->trans[i2][mloc];
        }
        // accumulate y for survivors; warp owns tokens with i%8 == wid
        unsigned nc = S->cnt;
        if (nc > 2048u) nc = 2048u;
        for (unsigned e = 0; e < nc; e++) {
            unsigned meta = S->list[e].x;
            int i = meta >> 11;
            if ((i & 7) != wid) continue;
            int m = meta & 2047;
            float a = __uint_as_float(S->list[e].y);
            const float4* wr = (const float4*)(w + (size_t)m * FEA);
            float4* yr = (float4*)S->ys[i];
#pragma unroll
            for (int k = 0; k < 4; k++) {
                float4 wv = wr[lane + 32 * k];
                float4 yv = yr[lane + 32 * k];
                yv.x += a * wv.x; yv.y += a * wv.y;
                yv.z += a * wv.z; yv.w += a * wv.w;
                yr[lane + 32 * k] = yv;
            }
        }
        __syncthreads();
    }
    // write y (coalesced over hw)
    for (int idx = tid; idx < 32 * FEA; idx += 256) {
        int i = idx & 31, c = idx >> 5;
        y_out[((size_t)b * FEA + c) * HW + hw0 + i] = S->ys[i][c];
    }
}

// ---------------- launcher ----------------
extern "C" void kernel_launch(void* const* d_in, const int* in_sizes, int n_in,
                              void* d_out, int out_size) {
    const float* x = (const float*)d_in[0];
    const float* w = (const float*)d_in[1];
    if (n_in >= 2 && in_sizes[0] == MEM_DIM * FEA && in_sizes[1] != MEM_DIM * FEA) {
        const float* t = x; x = w; w = t;
    }
    float* y_out   = (float*)d_out;                       // 32*512*32*32
    float* att_out = y_out + (size_t)NB * FEA * HW;       // 32*2000*32*32

    cudaFuncSetAttribute(k_out, cudaFuncAttributeMaxDynamicSharedMemorySize,
                         (int)sizeof(SmemC));

    k_prep<<<dim3(MPAD / 32, FEA / 32), 256>>>(w);
    k_gemm_exp<<<dim3(MPAD / BN, NTOK / BM), 256>>>(x);   // (16, 256)
    k_reset<<<1, 1>>>();
    k_stats<<<NTOK / 8, 256>>>();
    k_refine_patch<<<64, 256>>>(x, w);
    k_refine_norm<<<64, 256>>>();
    k_out<<<NTOK / 32, 256, sizeof(SmemC)>>>(w, y_out, att_out);
}

// round 8
// speedup vs baseline: 1.1300x; 1.0674x over previous
#include <cuda_runtime.h>
#include <math.h>
#include <cstdint>

#define MEM_DIM 2000
#define MPAD    2048
#define FEA     512
#define NB      32
#define HW      1024
#define NTOK    (NB * HW)      // 32768
#define THRES   0.0025f
#define EPSV    1e-12f
#define FIX_CAP 65536

// ---------------- scratch (static device allocations) ----------------
__device__ float  g_E[(size_t)NTOK * MEM_DIM];   // exp(logits), 262 MB
__device__ float  g_Wt[(size_t)FEA * MPAD];      // W transposed+padded, 4 MB
__device__ float  g_invS[NTOK];
__device__ double g_S64[NTOK];
__device__ float  g_invT[NTOK];
__device__ unsigned g_fix[FIX_CAP];
__device__ unsigned g_nfix;

// ---------------- helpers ----------------
__device__ __forceinline__ unsigned long long pack2(float v) {
    unsigned long long r;
    unsigned u = __float_as_uint(v);
    asm("mov.b64 %0, {%1, %1};" : "=l"(r) : "r"(u));
    return r;
}
__device__ __forceinline__ void fma2(unsigned long long &c, unsigned long long a, unsigned long long b) {
    asm("fma.rn.f32x2 %0, %1, %2, %0;" : "+l"(c) : "l"(a), "l"(b));
}
__device__ __forceinline__ float lo2(unsigned long long v) { return __uint_as_float((unsigned)v); }
__device__ __forceinline__ float hi2(unsigned long long v) { return __uint_as_float((unsigned)(v >> 32)); }

__device__ __forceinline__ unsigned sm2u(const void* p) {
    return (unsigned)__cvta_generic_to_shared(p);
}
#define CPA16(dst, src) asm volatile("cp.async.cg.shared.global [%0], [%1], 16;" :: "r"(dst), "l"(src))
#define CPCOMMIT()      asm volatile("cp.async.commit_group;")
#define CPWAIT(n)       asm volatile("cp.async.wait_group %0;" :: "n"(n))

// ---------------- kernel P: W[2000][512] -> Wt[512][2048] (pad zeros) -------
__global__ __launch_bounds__(256) void k_prep(const float* __restrict__ w) {
    __shared__ float t[32][33];
    int m0 = blockIdx.x * 32;
    int k0 = blockIdx.y * 32;
    int tx = threadIdx.x & 31, ty = threadIdx.x >> 5;   // 32 x 8
#pragma unroll
    for (int j = 0; j < 32; j += 8) {
        int m = m0 + ty + j;
        t[ty + j][tx] = (m < MEM_DIM) ? w[(size_t)m * FEA + k0 + tx] : 0.f;
    }
    __syncthreads();
#pragma unroll
    for (int j = 0; j < 32; j += 8)
        g_Wt[(size_t)(k0 + ty + j) * MPAD + m0 + tx] = t[tx][ty + j];
}

// ---------------- kernel A: logits GEMM + exp --------------------------------
// E[n, m] = exp( sum_c x[b,c,hw] * W[m,c] ),  n = b*1024 + hw
#define BM 128
#define BN 128
#define BKK 32
#define NCH (FEA / BKK)   // 16
// dynamic smem layout: As [2][BKK][BM] then Bs [2][BKK][BN]
#define GEMM_SMEM (2 * BKK * (BM + BN) * 4)   // 65536

__global__ __launch_bounds__(256, 2) void k_gemm_exp(const float* __restrict__ x) {
    extern __shared__ float smf[];
    float* As = smf;                       // [2][32][128]
    float* Bs = smf + 2 * BKK * BM;        // [2][32][128]
    const int tid = threadIdx.x;
    const int tx = tid & 15;
    const int ty = tid >> 4;
    const int m0 = blockIdx.x * BN;
    const int n0 = blockIdx.y * BM;
    const int b  = n0 >> 10;
    const int hw0 = n0 & 1023;
    const float* xb = x + (size_t)b * FEA * HW + hw0;

    const int lc  = tid >> 3;              // 0..31 (channel for loads)
    const int lsg = (tid & 7) * 16;        // 0..112 (float idx step 16, we do 4 cols of float4)

    unsigned long long acc[8][4];
#pragma unroll
    for (int i = 0; i < 8; i++)
#pragma unroll
        for (int j = 0; j < 4; j++) acc[i][j] = 0ull;

    // stage loader: 256 threads x 4 float4 each for A and B (32ch x 128 floats each)
    // thread handles channel lc, 4 consecutive float4 at lsg
#define LOAD_STAGE(s, k0)                                                              \
    do {                                                                               \
        const float* xa = xb + (size_t)((k0) + lc) * HW + lsg;                         \
        const float* wb = g_Wt + (size_t)((k0) + lc) * MPAD + m0 + lsg;                \
        uint32_t da = sm2u(&As[((s) * BKK + lc) * BM + lsg]);                          \
        uint32_t db = sm2u(&Bs[((s) * BKK + lc) * BN + lsg]);                          \
        CPA16(da,      xa);      CPA16(da + 16, xa + 4);                               \
        CPA16(da + 32, xa + 8);  CPA16(da + 48, xa + 12);                              \
        CPA16(db,      wb);      CPA16(db + 16, wb + 4);                               \
        CPA16(db + 32, wb + 8);  CPA16(db + 48, wb + 12);                              \
        CPCOMMIT();                                                                    \
    } while (0)

    LOAD_STAGE(0, 0);

    for (int it = 0; it < NCH; it++) {
        const int cur = it & 1;
        CPWAIT(0);
        __syncthreads();
        if (it + 1 < NCH) LOAD_STAGE(cur ^ 1, (it + 1) * BKK);
        const float* Ac = &As[cur * BKK * BM];
        const float* Bc = &Bs[cur * BKK * BN];
#pragma unroll
        for (int k = 0; k < BKK; k++) {
            float4 a0 = *(const float4*)&Ac[k * BM + ty * 8];
            float4 a1 = *(const float4*)&Ac[k * BM + ty * 8 + 4];
            const unsigned long long* bp = (const unsigned long long*)&Bc[k * BN + tx * 8];
            unsigned long long b0 = bp[0], b1 = bp[1], b2 = bp[2], b3 = bp[3];
            float av[8] = {a0.x, a0.y, a0.z, a0.w, a1.x, a1.y, a1.z, a1.w};
#pragma unroll
            for (int i = 0; i < 8; i++) {
                unsigned long long ap = pack2(av[i]);
                fma2(acc[i][0], ap, b0);
                fma2(acc[i][1], ap, b1);
                fma2(acc[i][2], ap, b2);
                fma2(acc[i][3], ap, b3);
            }
        }
    }

    const int m = m0 + tx * 8;
    if (m < MEM_DIM) {
#pragma unroll
        for (int i = 0; i < 8; i++) {
            int n = n0 + ty * 8 + i;
            float4 o0, o1;
            o0.x = __expf(lo2(acc[i][0])); o0.y = __expf(hi2(acc[i][0]));
            o0.z = __expf(lo2(acc[i][1])); o0.w = __expf(hi2(acc[i][1]));
            o1.x = __expf(lo2(acc[i][2])); o1.y = __expf(hi2(acc[i][2]));
            o1.z = __expf(lo2(acc[i][3])); o1.w = __expf(hi2(acc[i][3]));
            float* dst = &g_E[(size_t)n * MEM_DIM + m];
            *(float4*)dst = o0;
            *(float4*)(dst + 4) = o1;
        }
    }
}

// ---------------- counter reset ----------------
__global__ void k_reset() { g_nfix = 0u; }

// ---------------- kernel B: fused stats (streaming, cheap fp64) ----------------
// warp per row; pass1: sum with fp32 pairwise over groups of 8, fp64 across
// pass2 (L1-hot): shrink norm + borderline flags
__global__ __launch_bounds__(256) void k_stats() {
    int n = blockIdx.x * 8 + (threadIdx.x >> 5);
    int lane = threadIdx.x & 31;
    const float4* row4 = (const float4*)(g_E + (size_t)n * MEM_DIM);

    double s = 0.0;
#pragma unroll
    for (int i = 0; i < 8; i++) {
        int g = lane + 32 * i;          // pair index, 250 pairs of 8 floats
        if (g < 250) {
            float4 v0 = row4[2 * g];
            float4 v1 = row4[2 * g + 1];
            float p = ((v0.x + v0.y) + (v0.z + v0.w)) + ((v1.x + v1.y) + (v1.z + v1.w));
            s += (double)p;
        }
    }
#pragma unroll
    for (int o = 16; o; o >>= 1) s += __shfl_xor_sync(0xffffffffu, s, o);
    float is = (float)(1.0 / s);

    float t = 0.f;
#pragma unroll
    for (int i = 0; i < 16; i++) {
        int i4 = lane + 32 * i;
        if (i4 < 500) {
            float4 v = row4[i4];
            float e[4] = {v.x, v.y, v.z, v.w};
#pragma unroll
            for (int c = 0; c < 4; c++) {
                float att = e[c] * is;
                float d = att - THRES;
                if (d > 0.f) t += d * att / (d + EPSV);
                if (fabsf(att - THRES) < 5e-7f) {
                    unsigned idx = atomicAdd(&g_nfix, 1u);
                    if (idx < FIX_CAP) g_fix[idx] = ((unsigned)n << 11) | (unsigned)(i4 * 4 + c);
                }
            }
        }
    }
#pragma unroll
    for (int o = 16; o; o >>= 1) t += __shfl_xor_sync(0xffffffffu, t, o);
    if (lane == 0) {
        g_S64[n]  = s;
        g_invS[n] = is;
        g_invT[n] = 1.0f / fmaxf(t, EPSV);
    }
}

// ---------------- kernel B2: fp64 refinement (patch E) ----------------
__global__ __launch_bounds__(256) void k_refine_patch(const float* __restrict__ x,
                                                      const float* __restrict__ w) {
    unsigned total = g_nfix;
    if (total > FIX_CAP) total = FIX_CAP;
    int lane = threadIdx.x & 31;
    int warp = (blockIdx.x * 256 + threadIdx.x) >> 5;
    const int nwarps = 64 * 8;
    for (unsigned i = warp; i < total; i += nwarps) {
        unsigned code = g_fix[i];
        int n = code >> 11;
        int m = code & 2047;
        int b = n >> 10, hw = n & 1023;
        const float* xr = x + (size_t)b * FEA * HW + hw;
        const float* wr = w + (size_t)m * FEA;
        double s = 0.0;
#pragma unroll
        for (int k = 0; k < 16; k++) {
            int c = lane * 16 + k;
            s += (double)xr[(size_t)c * HW] * (double)wr[c];
        }
#pragma unroll
        for (int o = 16; o; o >>= 1) s += __shfl_xor_sync(0xffffffffu, s, o);
        if (lane == 0) {
            double S = g_S64[n];
            double att = exp(s) / S;
            const double T = 0.0025, MARGIN = 5e-9;
            double att_f = att;
            if (att > T) { if (att < T + MARGIN) att_f = T + MARGIN; }
            else         { if (att > T - MARGIN) att_f = T - MARGIN; }
            g_E[(size_t)n * MEM_DIM + m] = (float)(att_f * S);
        }
    }
}

// ---------------- kernel B3: recompute shrink norm for patched rows ----------
__global__ __launch_bounds__(256) void k_refine_norm() {
    unsigned total = g_nfix;
    if (total > FIX_CAP) total = FIX_CAP;
    int lane = threadIdx.x & 31;
    int warp = (blockIdx.x * 256 + threadIdx.x) >> 5;
    const int nwarps = 64 * 8;
    for (unsigned i = warp; i < total; i += nwarps) {
        int n = g_fix[i] >> 11;
        const float* row = g_E + (size_t)n * MEM_DIM;
        float is = g_invS[n];
        float t = 0.f;
        for (int j = lane; j < MEM_DIM; j += 32) {
            float att = row[j] * is;
            float d = att - THRES;
            if (d > 0.f) t += d * att / (d + EPSV);
        }
#pragma unroll
        for (int o = 16; o; o >>= 1) t += __shfl_xor_sync(0xffffffffu, t, o);
        if (lane == 0) g_invT[n] = 1.0f / fmaxf(t, EPSV);
    }
}

// ---------------- kernel C: fused att transpose-out + sparse y ----------------
struct SmemC {
    float ys[32][520];        // y accumulators (32 tokens x 512 ch)
    float trans[32][65];      // att transpose staging
    float sInv[32];
    float tInv[32];
    unsigned cnt;
    unsigned pad_;
    uint2 list[2048];         // survivor list: (token<<11|m, value)
};

__global__ __launch_bounds__(256) void k_out(const float* __restrict__ w,
                                             float* __restrict__ y_out,
                                             float* __restrict__ att_out) {
    extern __shared__ char smem_raw[];
    SmemC* S = (SmemC*)smem_raw;
    const int tid = threadIdx.x;
    const int wid = tid >> 5, lane = tid & 31;
    const int n0 = blockIdx.x * 32;
    const int b = n0 >> 10, hw0 = n0 & 1023;

    {
        float4* yp = (float4*)S->ys;
        for (int idx = tid; idx < 32 * 130; idx += 256)
            yp[idx] = make_float4(0.f, 0.f, 0.f, 0.f);
        if (tid < 32) {
            S->sInv[tid] = g_invS[n0 + tid];
            S->tInv[tid] = g_invT[n0 + tid];
        }
    }
    __syncthreads();

    const int moff = tid & 63;
    const int trow = tid >> 6;   // 0..3
    const int i2 = tid & 31;

    for (int mt = 0; mt < MEM_DIM; mt += 64) {
        if (tid == 0) S->cnt = 0;
        __syncthreads();
#pragma unroll
        for (int p = 0; p < 8; p++) {
            int i = p * 4 + trow;
            int m = mt + moff;
            float o = 0.f;
            if (m < MEM_DIM) {
                float e = g_E[(size_t)(n0 + i) * MEM_DIM + m];
                float att = e * S->sInv[i];
                float d = att - THRES;
                if (d > 0.f) {
                    o = (d * att / (d + EPSV)) * S->tInv[i];
                    unsigned slot = atomicAdd(&S->cnt, 1u);
                    S->list[slot] = make_uint2(((unsigned)i << 11) | (unsigned)m,
                                               __float_as_uint(o));
                }
            }
            S->trans[i][moff] = o;
        }
        __syncthreads();
#pragma unroll
        for (int p = 0; p < 8; p++) {
            int mloc = (tid >> 5) + p * 8;
            int m = mt + mloc;
            if (m < MEM_DIM)
                att_out[((size_t)b * MEM_DIM + m) * HW + hw0 + i2] = S->trans[i2][mloc];
        }
        unsigned nc = S->cnt;
        if (nc > 2048u) nc = 2048u;
        for (unsigned e = 0; e < nc; e++) {
            unsigned meta = S->list[e].x;
            int i = meta >> 11;
            if ((i & 7) != wid) continue;
            int m = meta & 2047;
            float a = __uint_as_float(S->list[e].y);
            const float4* wr = (const float4*)(w + (size_t)m * FEA);
            float4* yr = (float4*)S->ys[i];
#pragma unroll
            for (int k = 0; k < 4; k++) {
                float4 wv = wr[lane + 32 * k];
                float4 yv = yr[lane + 32 * k];
                yv.x += a * wv.x; yv.y += a * wv.y;
                yv.z += a * wv.z; yv.w += a * wv.w;
                yr[lane + 32 * k] = yv;
            }
        }
        __syncthreads();
    }
    for (int idx = tid; idx < 32 * FEA; idx += 256) {
        int i = idx & 31, c = idx >> 5;
        y_out[((size_t)b * FEA + c) * HW + hw0 + i] = S->ys[i][c];
    }
}

// ---------------- launcher ----------------
extern "C" void kernel_launch(void* const* d_in, const int* in_sizes, int n_in,
                              void* d_out, int out_size) {
    const float* x = (const float*)d_in[0];
    const float* w = (const float*)d_in[1];
    if (n_in >= 2 && in_sizes[0] == MEM_DIM * FEA && in_sizes[1] != MEM_DIM * FEA) {
        const float* t = x; x = w; w = t;
    }
    float* y_out   = (float*)d_out;                       // 32*512*32*32
    float* att_out = y_out + (size_t)NB * FEA * HW;       // 32*2000*32*32

    cudaFuncSetAttribute(k_gemm_exp, cudaFuncAttributeMaxDynamicSharedMemorySize, GEMM_SMEM);
    cudaFuncSetAttribute(k_out, cudaFuncAttributeMaxDynamicSharedMemorySize,
                         (int)sizeof(SmemC));

    k_prep<<<dim3(MPAD / 32, FEA / 32), 256>>>(w);
    k_gemm_exp<<<dim3(MPAD / BN, NTOK / BM), 256, GEMM_SMEM>>>(x);   // (16, 256)
    k_reset<<<1, 1>>>();
    k_stats<<<NTOK / 8, 256>>>();
    k_refine_patch<<<64, 256>>>(x, w);
    k_refine_norm<<<64, 256>>>();
    k_out<<<NTOK / 32, 256, sizeof(SmemC)>>>(w, y_out, att_out);
}